// round 4
// baseline (speedup 1.0000x reference)
#include <cuda_runtime.h>

#define MAGIC_C 5.0f
#define NKERN 7

__device__ __forceinline__ float tanh_approx(float x) {
    float y;
    asm("tanh.approx.f32 %0, %1;" : "=f"(y) : "f"(x));
    return y;
}

__global__ void __launch_bounds__(256) quant_tanh_kernel(
    const float4* __restrict__ x,
    const float*  __restrict__ w,   // (7,2) row-major: w[2k]=a_k, w[2k+1]=b_k
    float4* __restrict__ out,
    int n4)
{
    // Uniform broadcast weight loads — L1-resident after first warp.
    float a[NKERN], b5[NKERN];
#pragma unroll
    for (int k = 0; k < NKERN; k++) {
        a[k]  = __ldg(&w[2 * k]);
        b5[k] = MAGIC_C * __ldg(&w[2 * k + 1]);
    }

    int i = blockIdx.x * blockDim.x + threadIdx.x;
    if (i >= n4) return;

    float4 v = x[i];

    float r0 = 0.f, r1 = 0.f, r2 = 0.f, r3 = 0.f;
#pragma unroll
    for (int k = 0; k < NKERN; k++) {
        float t0 = tanh_approx(fmaf(MAGIC_C, v.x, b5[k]));
        float t1 = tanh_approx(fmaf(MAGIC_C, v.y, b5[k]));
        float t2 = tanh_approx(fmaf(MAGIC_C, v.z, b5[k]));
        float t3 = tanh_approx(fmaf(MAGIC_C, v.w, b5[k]));
        r0 = fmaf(a[k], t0, r0);
        r1 = fmaf(a[k], t1, r1);
        r2 = fmaf(a[k], t2, r2);
        r3 = fmaf(a[k], t3, r3);
    }

    out[i] = make_float4(r0, r1, r2, r3);
}

extern "C" void kernel_launch(void* const* d_in, const int* in_sizes, int n_in,
                              void* d_out, int out_size)
{
    const float4* x = (const float4*)d_in[0];
    const float*  w = (const float*)d_in[1];
    float4* out = (float4*)d_out;

    int n  = in_sizes[0];       // 2048*4096 = 8388608
    int n4 = n / 4;             // 2097152  (divisible)

    const int threads = 256;
    int blocks = (n4 + threads - 1) / threads;   // 8192
    quant_tanh_kernel<<<blocks, threads>>>(x, w, out, n4);
}